// round 8
// baseline (speedup 1.0000x reference)
#include <cuda_runtime.h>
#include <cstdint>

// B=2, S=1024, H=4096, NH=32, NKV=8, HD=128, GROUPS=4, M=B*S=2048
// Projection GEMMs: int8 IMMA (mma.m16n8k32.s8), weights exact int8,
// activations 2-slice per-row quantized (x ~= s*(256*h+l), err ~1.5e-5).
// Attention mid: fused causal flash kernel on tf32 mma (unchanged from R7).

// ---------------- scratch (static __device__, no allocations) ----------------
__device__ static int8_t g_Wi8 [6144 * 4096];        // 25 MB q,k,v weights int8
__device__ static int8_t g_Woi8[4096 * 4096];        // 17 MB Wo int8
__device__ static int8_t g_Xh[2048 * 4096];          // X hi slice
__device__ static int8_t g_Xl[2048 * 4096];          // X lo slice
__device__ static float  g_sx[2048];                 // X per-row scale
__device__ static float  g_Q[2 * 32 * 1024 * 128];   // [B,NH,S,HD] tf32 vals
__device__ static float  g_K[2 * 8 * 1024 * 128];
__device__ static float  g_V[2 * 8 * 1024 * 128];
__device__ static float  g_AO[2048 * 4096];          // [B*S, NH*HD]
__device__ static int8_t g_AOh[2048 * 4096];
__device__ static int8_t g_AOl[2048 * 4096];
__device__ static float  g_sao[2048];

// ---------------- helpers ----------------
__device__ __forceinline__ float to_tf32(float x) {
    uint32_t u;
    asm("cvt.rna.tf32.f32 %0, %1;" : "=r"(u) : "f"(x));
    return __uint_as_float(u);
}
__device__ __forceinline__ void cpa16(void* dst, const void* src) {
    uint32_t s = static_cast<uint32_t>(__cvta_generic_to_shared(dst));
    asm volatile("cp.async.cg.shared.global [%0], [%1], 16;\n" :: "r"(s), "l"(src));
}
#define CP_COMMIT() asm volatile("cp.async.commit_group;\n")
#define CP_WAIT1()  asm volatile("cp.async.wait_group 1;\n")
#define CP_WAIT0()  asm volatile("cp.async.wait_group 0;\n")

__device__ __forceinline__ void mma_tf32(float d[4], const uint32_t a[4], const uint32_t b[2]) {
    asm volatile(
        "mma.sync.aligned.m16n8k8.row.col.f32.tf32.tf32.f32 "
        "{%0,%1,%2,%3},{%4,%5,%6,%7},{%8,%9},{%0,%1,%2,%3};\n"
        : "+f"(d[0]), "+f"(d[1]), "+f"(d[2]), "+f"(d[3])
        : "r"(a[0]), "r"(a[1]), "r"(a[2]), "r"(a[3]), "r"(b[0]), "r"(b[1]));
}
__device__ __forceinline__ void mma_s8(int d[4], const int a[4], int b0, int b1) {
    asm volatile(
        "mma.sync.aligned.m16n8k32.row.col.s32.s8.s8.s32 "
        "{%0,%1,%2,%3},{%4,%5,%6,%7},{%8,%9},{%0,%1,%2,%3};\n"
        : "+r"(d[0]), "+r"(d[1]), "+r"(d[2]), "+r"(d[3])
        : "r"(a[0]), "r"(a[1]), "r"(a[2]), "r"(a[3]), "r"(b0), "r"(b1));
}

// ---------------- prep kernels ----------------
// int32 weights -> int8 (exact). thread handles 16 values.
__global__ __launch_bounds__(256) void wi8_kernel(const int* __restrict__ src,
                                                  int8_t* __restrict__ dst, int n16) {
    int i = blockIdx.x * 256 + threadIdx.x;
    if (i >= n16) return;
    const int4* s = reinterpret_cast<const int4*>(src) + i * 4;
    int4 a = s[0], b = s[1], c = s[2], d = s[3];
    uint32_t p0 = (a.x & 255) | ((a.y & 255) << 8) | ((a.z & 255) << 16) | ((a.w & 255) << 24);
    uint32_t p1 = (b.x & 255) | ((b.y & 255) << 8) | ((b.z & 255) << 16) | ((b.w & 255) << 24);
    uint32_t p2 = (c.x & 255) | ((c.y & 255) << 8) | ((c.z & 255) << 16) | ((c.w & 255) << 24);
    uint32_t p3 = (d.x & 255) | ((d.y & 255) << 8) | ((d.z & 255) << 16) | ((d.w & 255) << 24);
    reinterpret_cast<uint4*>(dst)[i] = make_uint4(p0, p1, p2, p3);
}

// per-row 2-slice int8 quantization of a [rows][4096] fp32 matrix.
__global__ __launch_bounds__(256) void rowquant_kernel(const float* __restrict__ src,
    int8_t* __restrict__ hi, int8_t* __restrict__ lo, float* __restrict__ sc)
{
    const int row = blockIdx.x, t = threadIdx.x;
    const float* x = src + (size_t)row * 4096;
    float4 v[4];
    float am = 0.f;
#pragma unroll
    for (int i = 0; i < 4; ++i) {
        v[i] = *reinterpret_cast<const float4*>(x + t * 16 + i * 4);
        am = fmaxf(am, fmaxf(fmaxf(fabsf(v[i].x), fabsf(v[i].y)),
                             fmaxf(fabsf(v[i].z), fabsf(v[i].w))));
    }
    __shared__ float red[8];
#pragma unroll
    for (int o = 16; o > 0; o >>= 1) am = fmaxf(am, __shfl_xor_sync(0xffffffffu, am, o));
    if ((t & 31) == 0) red[t >> 5] = am;
    __syncthreads();
    am = fmaxf(fmaxf(fmaxf(red[0], red[1]), fmaxf(red[2], red[3])),
               fmaxf(fmaxf(red[4], red[5]), fmaxf(red[6], red[7])));
    const float amc = fmaxf(am, 1e-30f);
    const float inv = 32512.f / amc;
    if (t == 0) sc[row] = amc / 32512.f;

    uint32_t hw[4], lw[4];
#pragma unroll
    for (int i = 0; i < 4; ++i) {
        float vv[4] = {v[i].x, v[i].y, v[i].z, v[i].w};
        uint32_t hword = 0, lword = 0;
#pragma unroll
        for (int c = 0; c < 4; ++c) {
            int q = __float2int_rn(vv[c] * inv);
            int h = (q + 128) >> 8;
            int l = q - (h << 8);
            hword |= (uint32_t)(h & 255) << (8 * c);
            lword |= (uint32_t)(l & 255) << (8 * c);
        }
        hw[i] = hword; lw[i] = lword;
    }
    *reinterpret_cast<uint4*>(hi + (size_t)row * 4096 + t * 16) = make_uint4(hw[0], hw[1], hw[2], hw[3]);
    *reinterpret_cast<uint4*>(lo + (size_t)row * 4096 + t * 16) = make_uint4(lw[0], lw[1], lw[2], lw[3]);
}

// ---------------- int8 GEMM core ----------------
// CTA 128x128, kc=128. smem per buffer: Ah/Al/B tiles, pitch 144 B.
#define KP 144
#define TILE_B (128 * KP)            // 18432
#define BUF_B  (3 * TILE_B)          // 55296
#define SMEM_I8 (2 * BUF_B)          // 110592

__device__ __forceinline__ void load_i8_tiles(char* dst, const int8_t* Ah,
                                              const int8_t* Al, const int8_t* Bp,
                                              int k0, int t) {
    int c = t & 7, r = t >> 3;                 // c: 16B chunk, r: 0..31
#pragma unroll
    for (int p = 0; p < 4; ++p) {
        int row = r + 32 * p;
        const size_t go = (size_t)row * 4096 + k0 + 16 * c;
        cpa16(dst + row * KP + 16 * c,              Ah + go);
        cpa16(dst + TILE_B + row * KP + 16 * c,     Al + go);
        cpa16(dst + 2 * TILE_B + row * KP + 16 * c, Bp + go);
    }
}

// one kc=128 chunk: warp tile 64x32 (4 m-tiles x 4 n-tiles), both slices.
__device__ __forceinline__ void compute_i8(const char* buf, int acch[4][4][4],
                                           int accl[4][4][4], int lane, int wm, int wn) {
    const int lr = lane >> 2, lc = lane & 3;
    const char* sAh = buf;
    const char* sAl = buf + TILE_B;
    const char* sB  = buf + 2 * TILE_B;
#pragma unroll
    for (int kk = 0; kk < 4; ++kk) {
        int ah[4][4], al[4][4];
#pragma unroll
        for (int i = 0; i < 4; ++i) {
            const char* pa = sAh + (wm + 16 * i + lr) * KP + kk * 32 + 4 * lc;
            ah[i][0] = *reinterpret_cast<const int*>(pa);
            ah[i][1] = *reinterpret_cast<const int*>(pa + 8 * KP);
            ah[i][2] = *reinterpret_cast<const int*>(pa + 16);
            ah[i][3] = *reinterpret_cast<const int*>(pa + 8 * KP + 16);
            const char* pl = sAl + (wm + 16 * i + lr) * KP + kk * 32 + 4 * lc;
            al[i][0] = *reinterpret_cast<const int*>(pl);
            al[i][1] = *reinterpret_cast<const int*>(pl + 8 * KP);
            al[i][2] = *reinterpret_cast<const int*>(pl + 16);
            al[i][3] = *reinterpret_cast<const int*>(pl + 8 * KP + 16);
        }
#pragma unroll
        for (int j = 0; j < 4; ++j) {
            const char* pb = sB + (wn + 8 * j + lr) * KP + kk * 32 + 4 * lc;
            int b0 = *reinterpret_cast<const int*>(pb);
            int b1 = *reinterpret_cast<const int*>(pb + 16);
#pragma unroll
            for (int i = 0; i < 4; ++i) {
                mma_s8(acch[i][j], ah[i], b0, b1);
                mma_s8(accl[i][j], al[i], b0, b1);
            }
        }
    }
}

// ---------------- GEMM 1: fused QKV projection (int8) ---------------- grid (16m, 48n)
__global__ __launch_bounds__(256) void qkv_i8(
    const float* __restrict__ sq, const float* __restrict__ bq,
    const float* __restrict__ sk, const float* __restrict__ bk,
    const float* __restrict__ sv)
{
    extern __shared__ char smc[];
    const int t = threadIdx.x, lane = t & 31, w = t >> 5;
    const int wm = (w >> 2) * 64, wn = (w & 3) * 32;
    const int m0 = blockIdx.x * 128, n0 = blockIdx.y * 128;

    int acch[4][4][4], accl[4][4][4];
#pragma unroll
    for (int i = 0; i < 4; ++i)
#pragma unroll
        for (int j = 0; j < 4; ++j)
#pragma unroll
            for (int q = 0; q < 4; ++q) { acch[i][j][q] = 0; accl[i][j][q] = 0; }

    const int8_t* Ah = g_Xh + (size_t)m0 * 4096;
    const int8_t* Al = g_Xl + (size_t)m0 * 4096;
    const int8_t* Bp = g_Wi8 + (size_t)n0 * 4096;

    load_i8_tiles(smc, Ah, Al, Bp, 0, t);
    CP_COMMIT();
    for (int it = 0; it < 32; ++it) {
        if (it + 1 < 32) {
            load_i8_tiles(smc + ((it + 1) & 1) * BUF_B, Ah, Al, Bp, (it + 1) * 128, t);
            CP_COMMIT();
            CP_WAIT1();
        } else CP_WAIT0();
        __syncthreads();
        compute_i8(smc + (it & 1) * BUF_B, acch, accl, lane, wm, wn);
        __syncthreads();
    }

    // epilogue: combine slices, dequant, bias, tf32 round, head scatter
    int region, nloc;
    const float* scale; const float* bias;
    if (n0 < 4096)      { region = 0; nloc = n0;        scale = sq; bias = bq; }
    else if (n0 < 5120) { region = 1; nloc = n0 - 4096; scale = sk; bias = bk; }
    else                { region = 2; nloc = n0 - 5120; scale = sv; bias = nullptr; }
    const int head = nloc >> 7;
    const int lr = lane >> 2, lc = lane & 3;
#pragma unroll
    for (int j = 0; j < 4; ++j) {
        int col = wn + 8 * j + 2 * lc;               // 0..127 within head
        int nl = nloc + col;
        float wsc0 = scale[nl], wsc1 = scale[nl + 1];
        float bb0 = bias ? bias[nl] : 0.f, bb1 = bias ? bias[nl + 1] : 0.f;
#pragma unroll
        for (int i = 0; i < 4; ++i) {
#pragma unroll
            for (int h2 = 0; h2 < 2; ++h2) {
                int m = m0 + wm + 16 * i + lr + 8 * h2;
                float sx = g_sx[m];
                int b = m >> 10, s = m & 1023;
                float v0 = to_tf32((256.f * (float)acch[i][j][2 * h2 + 0] +
                                    (float)accl[i][j][2 * h2 + 0]) * (sx * wsc0) + bb0);
                float v1 = to_tf32((256.f * (float)acch[i][j][2 * h2 + 1] +
                                    (float)accl[i][j][2 * h2 + 1]) * (sx * wsc1) + bb1);
                float* dst;
                if (region == 0)      dst = g_Q + ((size_t)((b * 32 + head) * 1024 + s)) * 128 + col;
                else if (region == 1) dst = g_K + ((size_t)((b * 8 + head) * 1024 + s)) * 128 + col;
                else                  dst = g_V + ((size_t)((b * 8 + head) * 1024 + s)) * 128 + col;
                *reinterpret_cast<float2*>(dst) = make_float2(v0, v1);
            }
        }
    }
}

// ---------------- GEMM 2: output projection (int8) ---------------- grid (16m, 32n)
__global__ __launch_bounds__(256) void o_i8(const float* __restrict__ so,
                                            float* __restrict__ out)
{
    extern __shared__ char smc[];
    const int t = threadIdx.x, lane = t & 31, w = t >> 5;
    const int wm = (w >> 2) * 64, wn = (w & 3) * 32;
    const int m0 = blockIdx.x * 128, n0 = blockIdx.y * 128;

    int acch[4][4][4], accl[4][4][4];
#pragma unroll
    for (int i = 0; i < 4; ++i)
#pragma unroll
        for (int j = 0; j < 4; ++j)
#pragma unroll
            for (int q = 0; q < 4; ++q) { acch[i][j][q] = 0; accl[i][j][q] = 0; }

    const int8_t* Ah = g_AOh + (size_t)m0 * 4096;
    const int8_t* Al = g_AOl + (size_t)m0 * 4096;
    const int8_t* Bp = g_Woi8 + (size_t)n0 * 4096;

    load_i8_tiles(smc, Ah, Al, Bp, 0, t);
    CP_COMMIT();
    for (int it = 0; it < 32; ++it) {
        if (it + 1 < 32) {
            load_i8_tiles(smc + ((it + 1) & 1) * BUF_B, Ah, Al, Bp, (it + 1) * 128, t);
            CP_COMMIT();
            CP_WAIT1();
        } else CP_WAIT0();
        __syncthreads();
        compute_i8(smc + (it & 1) * BUF_B, acch, accl, lane, wm, wn);
        __syncthreads();
    }

    const int lr = lane >> 2, lc = lane & 3;
#pragma unroll
    for (int j = 0; j < 4; ++j) {
        int col = n0 + wn + 8 * j + 2 * lc;
        float wsc0 = so[col], wsc1 = so[col + 1];
#pragma unroll
        for (int i = 0; i < 4; ++i) {
#pragma unroll
            for (int h2 = 0; h2 < 2; ++h2) {
                int m = m0 + wm + 16 * i + lr + 8 * h2;
                float sx = g_sao[m];
                float2 o = make_float2(
                    (256.f * (float)acch[i][j][2 * h2 + 0] + (float)accl[i][j][2 * h2 + 0]) * (sx * wsc0),
                    (256.f * (float)acch[i][j][2 * h2 + 1] + (float)accl[i][j][2 * h2 + 1]) * (sx * wsc1));
                *reinterpret_cast<float2*>(out + (size_t)m * 4096 + col) = o;
            }
        }
    }
}

// ---------------- fused causal flash attention (tf32) ---------------- grid (64, 8)
#define FK_PAD 132
#define FV_PAD 136
#define FP_PAD 68
#define SK_TILE (64 * FK_PAD)
#define SV_TILE (64 * FV_PAD)
#define FLASH_SMEM ((2 * SK_TILE + 2 * SV_TILE + 128 * FP_PAD) * 4)

__device__ __forceinline__ void flash_loadKV(float* dK, float* dV,
                                             const float* Kp, const float* Vp,
                                             int n0, int t) {
    int c = t & 31, rb = t >> 5;
#pragma unroll
    for (int p = 0; p < 8; ++p) {
        int r = rb + 8 * p;
        cpa16(dK + r * FK_PAD + 4 * c, Kp + (size_t)(n0 + r) * 128 + 4 * c);
        cpa16(dV + r * FV_PAD + 4 * c, Vp + (size_t)(n0 + r) * 128 + 4 * c);
    }
}

__global__ __launch_bounds__(256, 1) void flash_mma()
{
    extern __shared__ float sm[];
    float* sK = sm;
    float* sV = sm + 2 * SK_TILE;
    float* sP = sV + 2 * SV_TILE;

    const int t = threadIdx.x, lane = t & 31, w = t >> 5;
    const int lr = lane >> 2, lc = lane & 3;
    const int z = blockIdx.x, mt = 7 - blockIdx.y;
    const int m0 = mt * 128;
    const int niter = 2 * mt + 2;
    const int b = z >> 5, h = z & 31, kvh = h >> 2;

    const float* Qp = g_Q + (size_t)(b * 32 + h) * 131072;
    const float* Kp = g_K + (size_t)(b * 8 + kvh) * 131072;
    const float* Vp = g_V + (size_t)(b * 8 + kvh) * 131072;

    {
        int c = t & 31, rb = t >> 5;
#pragma unroll
        for (int p = 0; p < 16; ++p) {
            int r = rb + 8 * p;
            float* dst = (r < 64) ? (sK + r * FK_PAD + 4 * c)
                                  : (sV + (r - 64) * FV_PAD + 4 * c);
            cpa16(dst, Qp + (size_t)(m0 + r) * 128 + 4 * c);
        }
        CP_COMMIT(); CP_WAIT0();
    }
    __syncthreads();

    uint32_t qf[16][4];
    {
        const float* base; int pad, rb2;
        if (w < 4) { base = sK; pad = FK_PAD; rb2 = 16 * w; }
        else       { base = sV; pad = FV_PAD; rb2 = 16 * w - 64; }
#pragma unroll
        for (int s = 0; s < 16; ++s) {
            const float* p = base + (rb2 + lr) * pad + 8 * s + lc;
            qf[s][0] = __float_as_uint(p[0]);
            qf[s][1] = __float_as_uint(p[8 * pad]);
            qf[s][2] = __float_as_uint(p[4]);
            qf[s][3] = __float_as_uint(p[8 * pad + 4]);
        }
    }
    __syncthreads();

    float oacc[16][4];
#pragma unroll
    for (int j = 0; j < 16; ++j)
#pragma unroll
        for (int q = 0; q < 4; ++q) oacc[j][q] = 0.f;
    float mrow[2] = {-1e38f, -1e38f};
    float lrow[2] = {0.f, 0.f};

    flash_loadKV(sK, sV, Kp, Vp, 0, t);
    CP_COMMIT();

    const float sscale = 0.08838834764831845f;

    for (int it = 0; it < niter; ++it) {
        if (it + 1 < niter) {
            int nb = (it + 1) & 1;
            flash_loadKV(sK + nb * SK_TILE, sV + nb * SV_TILE, Kp, Vp, (it + 1) * 64, t);
            CP_COMMIT(); CP_WAIT1();
        } else CP_WAIT0();
        __syncthreads();

        const int buf = it & 1;
        const float* K0 = sK + buf * SK_TILE;
        const float* V0 = sV + buf * SV_TILE;
        const int n0 = it * 64;

        float sacc[8][4];
#pragma unroll
        for (int j = 0; j < 8; ++j)
#pragma unroll
            for (int q = 0; q < 4; ++q) sacc[j][q] = 0.f;
#pragma unroll
        for (int s = 0; s < 16; ++s) {
#pragma unroll
            for (int j = 0; j < 8; ++j) {
                uint32_t bf[2];
                const float* p = K0 + (8 * j + lr) * FK_PAD + 8 * s + lc;
                bf[0] = __float_as_uint(p[0]);
                bf[1] = __float_as_uint(p[4]);
                mma_tf32(sacc[j], qf[s], bf);
            }
        }

#pragma unroll
        for (int d = 0; d < 2; ++d) {
            const int grow = m0 + 16 * w + lr + 8 * d;
            float rm = -1e38f;
#pragma unroll
            for (int j = 0; j < 8; ++j) {
                int c0 = n0 + 8 * j + 2 * lc;
                float v0 = sacc[j][2 * d]     * sscale;
                float v1 = sacc[j][2 * d + 1] * sscale;
                if (c0     > grow) v0 = -1e30f;
                if (c0 + 1 > grow) v1 = -1e30f;
                sacc[j][2 * d]     = v0;
                sacc[j][2 * d + 1] = v1;
                rm = fmaxf(rm, fmaxf(v0, v1));
            }
            rm = fmaxf(rm, __shfl_xor_sync(0xffffffffu, rm, 1));
            rm = fmaxf(rm, __shfl_xor_sync(0xffffffffu, rm, 2));
            float newm = fmaxf(mrow[d], rm);
            float f = __expf(mrow[d] - newm);
            float rs = 0.f;
#pragma unroll
            for (int j = 0; j < 8; ++j) {
                float p0 = __expf(sacc[j][2 * d]     - newm);
                float p1 = __expf(sacc[j][2 * d + 1] - newm);
                rs += p0 + p1;
                float* pp = sP + (16 * w + lr + 8 * d) * FP_PAD + 8 * j + 2 * lc;
                pp[0] = to_tf32(p0);
                pp[1] = to_tf32(p1);
            }
            rs += __shfl_xor_sync(0xffffffffu, rs, 1);
            rs += __shfl_xor_sync(0xffffffffu, rs, 2);
            lrow[d] = lrow[d] * f + rs;
            mrow[d] = newm;
#pragma unroll
            for (int j2 = 0; j2 < 16; ++j2) {
                oacc[j2][2 * d]     *= f;
                oacc[j2][2 * d + 1] *= f;
            }
        }
        __syncwarp();

#pragma unroll
        for (int s = 0; s < 8; ++s) {
            uint32_t af[4];
            const float* pa = sP + (16 * w + lr) * FP_PAD + 8 * s + lc;
            af[0] = __float_as_uint(pa[0]);
            af[1] = __float_as_uint(pa[8 * FP_PAD]);
            af[2] = __float_as_uint(pa[4]);
            af[3] = __float_as_uint(pa[8 * FP_PAD + 4]);
#pragma unroll
            for (int j2 = 0; j2 < 16; ++j2) {
                uint32_t bf[2];
                const float* pb = V0 + (8 * s + lc) * FV_PAD + 8 * j2 + lr;
                bf[0] = __float_as_uint(pb[0]);
                bf[1] = __float_as_uint(pb[4 * FV_PAD]);
                mma_tf32(oacc[j2], af, bf);
            }
        }
        __syncthreads();
    }

#pragma unroll
    for (int d = 0; d < 2; ++d) {
        float inv = 1.f / lrow[d];
        int grow = m0 + 16 * w + lr + 8 * d;
        float* orow = g_AO + ((size_t)(b * 1024 + grow)) * 4096 + h * 128;
#pragma unroll
        for (int j2 = 0; j2 < 16; ++j2) {
            float2 o = make_float2(oacc[j2][2 * d]     * inv,
                                   oacc[j2][2 * d + 1] * inv);
            *reinterpret_cast<float2*>(orow + 8 * j2 + 2 * lc) = o;
        }
    }
}

// =============================================================================
extern "C" void kernel_launch(void* const* d_in, const int* in_sizes, int n_in,
                              void* d_out, int out_size)
{
    const float* X    = (const float*)d_in[0];
    const float* sq   = (const float*)d_in[3];
    const float* bq   = (const float*)d_in[4];
    const float* sk   = (const float*)d_in[6];
    const float* bk   = (const float*)d_in[7];
    const float* sv   = (const float*)d_in[9];
    const float* so   = (const float*)d_in[11];
    const int*   wq   = (const int*)d_in[2];
    const int*   wk   = (const int*)d_in[5];
    const int*   wv   = (const int*)d_in[8];
    const int*   wo   = (const int*)d_in[10];
    float* out = (float*)d_out;

    cudaFuncSetAttribute(qkv_i8,    cudaFuncAttributeMaxDynamicSharedMemorySize, SMEM_I8);
    cudaFuncSetAttribute(o_i8,      cudaFuncAttributeMaxDynamicSharedMemorySize, SMEM_I8);
    cudaFuncSetAttribute(flash_mma, cudaFuncAttributeMaxDynamicSharedMemorySize, FLASH_SMEM);

    int8_t* Wi8 = nullptr;  cudaGetSymbolAddress((void**)&Wi8,  g_Wi8);
    int8_t* Woi8 = nullptr; cudaGetSymbolAddress((void**)&Woi8, g_Woi8);
    int8_t* Xh = nullptr;   cudaGetSymbolAddress((void**)&Xh,   g_Xh);
    int8_t* Xl = nullptr;   cudaGetSymbolAddress((void**)&Xl,   g_Xl);
    float*  sx = nullptr;   cudaGetSymbolAddress((void**)&sx,   g_sx);
    float*  AO = nullptr;   cudaGetSymbolAddress((void**)&AO,   g_AO);
    int8_t* AOh = nullptr;  cudaGetSymbolAddress((void**)&AOh,  g_AOh);
    int8_t* AOl = nullptr;  cudaGetSymbolAddress((void**)&AOl,  g_AOl);
    float*  sao = nullptr;  cudaGetSymbolAddress((void**)&sao,  g_sao);

    // prep: quantize X (2-slice), weights int32 -> int8 (exact)
    rowquant_kernel<<<2048, 256>>>(X, Xh, Xl, sx);
    wi8_kernel<<<(4096 * 4096 / 16 + 255) / 256, 256>>>(wq, Wi8,               4096 * 4096 / 16);
    wi8_kernel<<<(1024 * 4096 / 16 + 255) / 256, 256>>>(wk, Wi8 + 4096 * 4096, 1024 * 4096 / 16);
    wi8_kernel<<<(1024 * 4096 / 16 + 255) / 256, 256>>>(wv, Wi8 + 5120 * 4096, 1024 * 4096 / 16);
    wi8_kernel<<<(4096 * 4096 / 16 + 255) / 256, 256>>>(wo, Woi8,              4096 * 4096 / 16);

    qkv_i8<<<dim3(16, 48), 256, SMEM_I8>>>(sq, bq, sk, bk, sv);
    flash_mma<<<dim3(64, 8), 256, FLASH_SMEM>>>();
    rowquant_kernel<<<2048, 256>>>(AO, AOh, AOl, sao);
    o_i8<<<dim3(16, 32), 256, SMEM_I8>>>(so, out);
}

// round 9
// speedup vs baseline: 4.1679x; 4.1679x over previous
#include <cuda_runtime.h>
#include <cuda_fp16.h>
#include <cstdint>

// B=2, S=1024, H=4096, NH=32, NKV=8, HD=128, GROUPS=4, M=B*S=2048
// All GEMMs: fp16 mma.m16n8k16 with fp32 accumulation.
// fp16 mantissa == tf32 mantissa (10 bits) -> same numerics as the tf32
// version, at 2x MACs/instruction. Weights (int8-valued) exact in fp16.

// ---------------- scratch (static __device__, no allocations) ----------------
__device__ static __half g_Xh[2048 * 4096];           // 16 MB fp16 X
__device__ static __half g_W [6144 * 4096];           // 50 MB q,k,v weights fp16
__device__ static __half g_Wo[4096 * 4096];           // 32 MB Wo fp16
__device__ static __half g_Q[2 * 32 * 1024 * 128];    // [B,NH,S,HD]
__device__ static __half g_K[2 * 8 * 1024 * 128];     // [B,NKV,S,HD]
__device__ static __half g_V[2 * 8 * 1024 * 128];     // [B,NKV,S/2,HD,2] k-pair interleaved
__device__ static __half g_AO[2048 * 4096];           // [B*S, NH*HD]

// ---------------- helpers ----------------
__device__ __forceinline__ void cpa16(void* dst, const void* src) {
    uint32_t s = static_cast<uint32_t>(__cvta_generic_to_shared(dst));
    asm volatile("cp.async.cg.shared.global [%0], [%1], 16;\n" :: "r"(s), "l"(src));
}
#define CP_COMMIT() asm volatile("cp.async.commit_group;\n")
#define CP_WAIT1()  asm volatile("cp.async.wait_group 1;\n")
#define CP_WAIT0()  asm volatile("cp.async.wait_group 0;\n")

__device__ __forceinline__ void mma_f16(float d[4], const uint32_t a[4], uint32_t b0, uint32_t b1) {
    asm volatile(
        "mma.sync.aligned.m16n8k16.row.col.f32.f16.f16.f32 "
        "{%0,%1,%2,%3},{%4,%5,%6,%7},{%8,%9},{%0,%1,%2,%3};\n"
        : "+f"(d[0]), "+f"(d[1]), "+f"(d[2]), "+f"(d[3])
        : "r"(a[0]), "r"(a[1]), "r"(a[2]), "r"(a[3]), "r"(b0), "r"(b1));
}
__device__ __forceinline__ uint32_t ldu32(const __half* p) {
    return *reinterpret_cast<const uint32_t*>(p);
}

// ---------------- prep kernels ----------------
// int32 weights -> fp16 (exact for |w|<=127). thread: 8 values.
__global__ __launch_bounds__(256) void w2h_kernel(const int* __restrict__ src,
                                                  __half* __restrict__ dst, int n8) {
    int i = blockIdx.x * 256 + threadIdx.x;
    if (i >= n8) return;
    const int4* s = reinterpret_cast<const int4*>(src) + i * 2;
    int4 a = s[0], b = s[1];
    __half h[8];
    h[0] = __int2half_rn(a.x); h[1] = __int2half_rn(a.y);
    h[2] = __int2half_rn(a.z); h[3] = __int2half_rn(a.w);
    h[4] = __int2half_rn(b.x); h[5] = __int2half_rn(b.y);
    h[6] = __int2half_rn(b.z); h[7] = __int2half_rn(b.w);
    reinterpret_cast<uint4*>(dst)[i] = *reinterpret_cast<const uint4*>(h);
}
// f32 -> f16. thread: 8 values.
__global__ __launch_bounds__(256) void x2h_kernel(const float* __restrict__ src,
                                                  __half* __restrict__ dst, int n8) {
    int i = blockIdx.x * 256 + threadIdx.x;
    if (i >= n8) return;
    const float4* s = reinterpret_cast<const float4*>(src) + i * 2;
    float4 a = s[0], b = s[1];
    __half h[8];
    h[0] = __float2half_rn(a.x); h[1] = __float2half_rn(a.y);
    h[2] = __float2half_rn(a.z); h[3] = __float2half_rn(a.w);
    h[4] = __float2half_rn(b.x); h[5] = __float2half_rn(b.y);
    h[6] = __float2half_rn(b.z); h[7] = __float2half_rn(b.w);
    reinterpret_cast<uint4*>(dst)[i] = *reinterpret_cast<const uint4*>(h);
}

// ---------------- fp16 GEMM core ----------------
// CTA 256x128, kc=64 halves. smem pitch 72 halves (144 B).
// A [256][72], B [128][72] halves. double buffered.
#define HP 72
#define AH (256 * HP)                 // halves per A tile
#define BH (128 * HP)
#define BUFH (AH + BH)
#define SMEM_H ((2 * BUFH) * 2)       // bytes = 110592

__device__ __forceinline__ void load_tileA_h(__half* dst, const __half* src, int rs, int t) {
    int c = t & 7, mb = t >> 3;       // 8 chunks of 16B per 128B row
#pragma unroll
    for (int p = 0; p < 8; ++p) {
        int m = mb + 32 * p;
        cpa16(dst + m * HP + 8 * c, src + (size_t)m * rs + 8 * c);
    }
}
__device__ __forceinline__ void load_tileB_h(__half* dst, const __half* src, int rs, int t) {
    int c = t & 7, nb = t >> 3;
#pragma unroll
    for (int p = 0; p < 4; ++p) {
        int n = nb + 32 * p;
        cpa16(dst + n * HP + 8 * c, src + (size_t)n * rs + 8 * c);
    }
}

// one kc=64 chunk (4 k16 steps). warp tile 64x64: 4 m-tiles x 8 n-tiles.
__device__ __forceinline__ void compute_h64(const __half* sA, const __half* sB,
                                            float acc[4][8][4], int lane, int wm, int wn) {
    const int lr = lane >> 2, lc = lane & 3;
#pragma unroll
    for (int ks = 0; ks < 4; ++ks) {
        uint32_t af[4][4], bf[8][2];
#pragma unroll
        for (int i = 0; i < 4; ++i) {
            const __half* p = sA + (wm + 16 * i + lr) * HP + 16 * ks + 2 * lc;
            af[i][0] = ldu32(p);
            af[i][1] = ldu32(p + 8 * HP);
            af[i][2] = ldu32(p + 8);
            af[i][3] = ldu32(p + 8 * HP + 8);
        }
#pragma unroll
        for (int j = 0; j < 8; ++j) {
            const __half* p = sB + (wn + 8 * j + lr) * HP + 16 * ks + 2 * lc;
            bf[j][0] = ldu32(p);
            bf[j][1] = ldu32(p + 8);
        }
#pragma unroll
        for (int i = 0; i < 4; ++i)
#pragma unroll
            for (int j = 0; j < 8; ++j)
                mma_f16(acc[i][j], af[i], bf[j][0], bf[j][1]);
    }
}

// ---------------- GEMM 1: fused QKV projection ---------------- grid (8m, 48n)
__global__ __launch_bounds__(256) void qkv_h(
    const float* __restrict__ sq, const float* __restrict__ bq,
    const float* __restrict__ sk, const float* __restrict__ bk,
    const float* __restrict__ sv)
{
    extern __shared__ __half smh[];
    __half* sA = smh;
    __half* sB = smh + 2 * AH;
    const int t = threadIdx.x, lane = t & 31, w = t >> 5;
    const int wm = (w >> 1) * 64, wn = (w & 1) * 64;
    const int m0 = blockIdx.x * 256, n0 = blockIdx.y * 128;

    float acc[4][8][4];
#pragma unroll
    for (int i = 0; i < 4; ++i)
#pragma unroll
        for (int j = 0; j < 8; ++j)
#pragma unroll
            for (int q = 0; q < 4; ++q) acc[i][j][q] = 0.f;

    const __half* Ab = g_Xh + (size_t)m0 * 4096;
    const __half* Bb = g_W + (size_t)n0 * 4096;

    load_tileA_h(sA, Ab, 4096, t);
    load_tileB_h(sB, Bb, 4096, t);
    CP_COMMIT();
    for (int it = 0; it < 64; ++it) {
        if (it + 1 < 64) {
            int nb = (it + 1) & 1;
            load_tileA_h(sA + nb * AH, Ab + (it + 1) * 64, 4096, t);
            load_tileB_h(sB + nb * BH, Bb + (it + 1) * 64, 4096, t);
            CP_COMMIT();
            CP_WAIT1();
        } else CP_WAIT0();
        __syncthreads();
        int buf = it & 1;
        compute_h64(sA + buf * AH, sB + buf * BH, acc, lane, wm, wn);
        __syncthreads();
    }

    // epilogue: dequant + bias + fp16 round + head scatter
    int region, nloc;
    const float* scale; const float* bias;
    if (n0 < 4096)      { region = 0; nloc = n0;        scale = sq; bias = bq; }
    else if (n0 < 5120) { region = 1; nloc = n0 - 4096; scale = sk; bias = bk; }
    else                { region = 2; nloc = n0 - 5120; scale = sv; bias = nullptr; }
    const int head = nloc >> 7;
    const int lr = lane >> 2, lc = lane & 3;
#pragma unroll
    for (int j = 0; j < 8; ++j) {
        int col = wn + 8 * j + 2 * lc;               // 0..127 within head
        int nl = nloc + col;
        float sc0 = scale[nl], sc1 = scale[nl + 1];
        float bb0 = bias ? bias[nl] : 0.f, bb1 = bias ? bias[nl + 1] : 0.f;
#pragma unroll
        for (int i = 0; i < 4; ++i) {
#pragma unroll
            for (int h2 = 0; h2 < 2; ++h2) {
                int m = m0 + wm + 16 * i + lr + 8 * h2;
                int b = m >> 10, s = m & 1023;
                float v0 = acc[i][j][2 * h2 + 0] * sc0 + bb0;
                float v1 = acc[i][j][2 * h2 + 1] * sc1 + bb1;
                if (region == 0) {
                    __half2* dst = reinterpret_cast<__half2*>(
                        g_Q + ((size_t)((b * 32 + head) * 1024 + s)) * 128 + col);
                    *dst = __floats2half2_rn(v0, v1);
                } else if (region == 1) {
                    __half2* dst = reinterpret_cast<__half2*>(
                        g_K + ((size_t)((b * 8 + head) * 1024 + s)) * 128 + col);
                    *dst = __floats2half2_rn(v0, v1);
                } else {
                    // V: k-pair interleaved [s/2][128][2]
                    __half* base = g_V + (size_t)(b * 8 + head) * 131072;
                    base[(size_t)(s >> 1) * 256 + col * 2 + (s & 1)]       = __float2half_rn(v0);
                    base[(size_t)(s >> 1) * 256 + (col + 1) * 2 + (s & 1)] = __float2half_rn(v1);
                }
            }
        }
    }
}

// ---------------- fused causal flash attention (fp16) ---------------- grid (64, 8)
// sK [2][64][136] halves, sV [2][32][272] halves (k-pair rows), sP [128][72].
#define FKH 136
#define FVH 272
#define FPH 72
#define SKH (64 * FKH)     // 8704 halves
#define SVH (32 * FVH)     // 8704 halves
#define FLASH_SMEM ((2 * SKH + 2 * SVH + 128 * FPH) * 2)   // 88064 B

__device__ __forceinline__ void flash_loadK(__half* dK, const __half* Kp, int n0, int t) {
    int c = t & 15, rb = t >> 4;
#pragma unroll
    for (int p = 0; p < 4; ++p) {
        int r = rb + 16 * p;
        cpa16(dK + r * FKH + 8 * c, Kp + (size_t)(n0 + r) * 128 + 8 * c);
    }
}
__device__ __forceinline__ void flash_loadV(__half* dV, const __half* Vp, int n0, int t) {
    int c = t & 31, rb = t >> 5;
#pragma unroll
    for (int p = 0; p < 4; ++p) {
        int r = rb + 8 * p;     // k2 row
        cpa16(dV + r * FVH + 8 * c, Vp + (size_t)((n0 >> 1) + r) * 256 + 8 * c);
    }
}

__global__ __launch_bounds__(256, 1) void flash_h()
{
    extern __shared__ __half smh[];
    __half* sK = smh;
    __half* sV = smh + 2 * SKH;
    __half* sP = sV + 2 * SVH;

    const int t = threadIdx.x, lane = t & 31, w = t >> 5;
    const int lr = lane >> 2, lc = lane & 3;
    const int z = blockIdx.x, mt = 7 - blockIdx.y;   // heavy tiles first
    const int m0 = mt * 128;
    const int niter = 2 * mt + 2;
    const int b = z >> 5, h = z & 31, kvh = h >> 2;

    const __half* Qp = g_Q + (size_t)(b * 32 + h) * 131072;
    const __half* Kp = g_K + (size_t)(b * 8 + kvh) * 131072;
    const __half* Vp = g_V + (size_t)(b * 8 + kvh) * 131072;

    // stage Q: rows 0-63 -> sK buf0 (pitch FKH), rows 64-127 -> sV buf0 (pitch FKH)
    {
        int c = t & 15, rb = t >> 4;
#pragma unroll
        for (int p = 0; p < 8; ++p) {
            int r = rb + 16 * p;
            __half* dst = (r < 64) ? (sK + r * FKH + 8 * c)
                                   : (sV + (r - 64) * FKH + 8 * c);
            cpa16(dst, Qp + (size_t)(m0 + r) * 128 + 8 * c);
        }
        CP_COMMIT(); CP_WAIT0();
    }
    __syncthreads();

    // extract Q fragments: 8 k16 steps x 4 regs
    uint32_t qf[8][4];
    {
        const __half* base = (w < 4) ? sK : sV;
        int rb2 = (w < 4) ? 16 * w : 16 * w - 64;
#pragma unroll
        for (int s = 0; s < 8; ++s) {
            const __half* p = base + (rb2 + lr) * FKH + 16 * s + 2 * lc;
            qf[s][0] = ldu32(p);
            qf[s][1] = ldu32(p + 8 * FKH);
            qf[s][2] = ldu32(p + 8);
            qf[s][3] = ldu32(p + 8 * FKH + 8);
        }
    }
    __syncthreads();

    float oacc[16][4];
#pragma unroll
    for (int j = 0; j < 16; ++j)
#pragma unroll
        for (int q = 0; q < 4; ++q) oacc[j][q] = 0.f;
    float mrow[2] = {-1e38f, -1e38f};
    float lrow[2] = {0.f, 0.f};

    flash_loadK(sK, Kp, 0, t);
    flash_loadV(sV, Vp, 0, t);
    CP_COMMIT();

    const float sscale = 0.08838834764831845f;   // 1/sqrt(128)

    for (int it = 0; it < niter; ++it) {
        if (it + 1 < niter) {
            int nb = (it + 1) & 1;
            flash_loadK(sK + nb * SKH, Kp, (it + 1) * 64, t);
            flash_loadV(sV + nb * SVH, Vp, (it + 1) * 64, t);
            CP_COMMIT(); CP_WAIT1();
        } else CP_WAIT0();
        __syncthreads();

        const int buf = it & 1;
        const __half* K0 = sK + buf * SKH;
        const __half* V0 = sV + buf * SVH;
        const int n0 = it * 64;

        // ---- S = Q K^T (warp: 16 rows x 64 keys), 8 k16 steps over d=128
        float sacc[8][4];
#pragma unroll
        for (int j = 0; j < 8; ++j)
#pragma unroll
            for (int q = 0; q < 4; ++q) sacc[j][q] = 0.f;
#pragma unroll
        for (int s = 0; s < 8; ++s) {
#pragma unroll
            for (int j = 0; j < 8; ++j) {
                const __half* p = K0 + (8 * j + lr) * FKH + 16 * s + 2 * lc;
                mma_f16(sacc[j], qf[s], ldu32(p), ldu32(p + 8));
            }
        }

        // ---- scale + causal mask + online softmax
#pragma unroll
        for (int d = 0; d < 2; ++d) {
            const int grow = m0 + 16 * w + lr + 8 * d;
            float rm = -1e38f;
#pragma unroll
            for (int j = 0; j < 8; ++j) {
                int c0 = n0 + 8 * j + 2 * lc;
                float v0 = sacc[j][2 * d]     * sscale;
                float v1 = sacc[j][2 * d + 1] * sscale;
                if (c0     > grow) v0 = -1e30f;
                if (c0 + 1 > grow) v1 = -1e30f;
                sacc[j][2 * d]     = v0;
                sacc[j][2 * d + 1] = v1;
                rm = fmaxf(rm, fmaxf(v0, v1));
            }
            rm = fmaxf(rm, __shfl_xor_sync(0xffffffffu, rm, 1));
            rm = fmaxf(rm, __shfl_xor_sync(0xffffffffu, rm, 2));
            float newm = fmaxf(mrow[d], rm);
            float f = __expf(mrow[d] - newm);
            float rs = 0.f;
#pragma unroll
            for (int j = 0; j < 8; ++j) {
                float p0 = __expf(sacc[j][2 * d]     - newm);
                float p1 = __expf(sacc[j][2 * d + 1] - newm);
                rs += p0 + p1;
                __half2* pp = reinterpret_cast<__half2*>(
                    sP + (16 * w + lr + 8 * d) * FPH + 8 * j + 2 * lc);
                *pp = __floats2half2_rn(p0, p1);
            }
            rs += __shfl_xor_sync(0xffffffffu, rs, 1);
            rs += __shfl_xor_sync(0xffffffffu, rs, 2);
            lrow[d] = lrow[d] * f + rs;
            mrow[d] = newm;
#pragma unroll
            for (int j2 = 0; j2 < 16; ++j2) {
                oacc[j2][2 * d]     *= f;
                oacc[j2][2 * d + 1] *= f;
            }
        }
        __syncwarp();

        // ---- O += P V  (warp: 16 rows x 128 d), 4 k16 steps over 64 keys
#pragma unroll
        for (int s = 0; s < 4; ++s) {
            uint32_t af[4];
            const __half* pa = sP + (16 * w + lr) * FPH + 16 * s + 2 * lc;
            af[0] = ldu32(pa);
            af[1] = ldu32(pa + 8 * FPH);
            af[2] = ldu32(pa + 8);
            af[3] = ldu32(pa + 8 * FPH + 8);
#pragma unroll
            for (int j2 = 0; j2 < 16; ++j2) {
                // V pair-interleaved: u32 at (k2)*136 + d  (u32 units)
                const uint32_t* vb = reinterpret_cast<const uint32_t*>(V0);
                uint32_t b0 = vb[(8 * s + lc) * 136 + 8 * j2 + lr];
                uint32_t b1 = vb[(8 * s + lc + 4) * 136 + 8 * j2 + lr];
                mma_f16(oacc[j2], af, b0, b1);
            }
        }
        __syncthreads();
    }

    // ---- epilogue: O /= l, fp16 round, write [B*S, NH*HD]
#pragma unroll
    for (int d = 0; d < 2; ++d) {
        float inv = 1.f / lrow[d];
        int grow = m0 + 16 * w + lr + 8 * d;
        __half* orow = g_AO + ((size_t)(b * 1024 + grow)) * 4096 + h * 128;
#pragma unroll
        for (int j2 = 0; j2 < 16; ++j2) {
            __half2* dst = reinterpret_cast<__half2*>(orow + 8 * j2 + 2 * lc);
            *dst = __floats2half2_rn(oacc[j2][2 * d] * inv, oacc[j2][2 * d + 1] * inv);
        }
    }
}

// ---------------- GEMM 4: out = AO @ Wo^T * so ---------------- grid (8m, 32n)
__global__ __launch_bounds__(256) void o_h(const float* __restrict__ so,
                                           float* __restrict__ out)
{
    extern __shared__ __half smh[];
    __half* sA = smh;
    __half* sB = smh + 2 * AH;
    const int t = threadIdx.x, lane = t & 31, w = t >> 5;
    const int wm = (w >> 1) * 64, wn = (w & 1) * 64;
    const int m0 = blockIdx.x * 256, n0 = blockIdx.y * 128;

    float acc[4][8][4];
#pragma unroll
    for (int i = 0; i < 4; ++i)
#pragma unroll
        for (int j = 0; j < 8; ++j)
#pragma unroll
            for (int q = 0; q < 4; ++q) acc[i][j][q] = 0.f;

    const __half* Ab = g_AO + (size_t)m0 * 4096;
    const __half* Bb = g_Wo + (size_t)n0 * 4096;
    load_tileA_h(sA, Ab, 4096, t);
    load_tileB_h(sB, Bb, 4096, t);
    CP_COMMIT();
    for (int it = 0; it < 64; ++it) {
        if (it + 1 < 64) {
            int nb = (it + 1) & 1;
            load_tileA_h(sA + nb * AH, Ab + (it + 1) * 64, 4096, t);
            load_tileB_h(sB + nb * BH, Bb + (it + 1) * 64, 4096, t);
            CP_COMMIT();
            CP_WAIT1();
        } else CP_WAIT0();
        __syncthreads();
        int buf = it & 1;
        compute_h64(sA + buf * AH, sB + buf * BH, acc, lane, wm, wn);
        __syncthreads();
    }

    const int lr = lane >> 2, lc = lane & 3;
#pragma unroll
    for (int j = 0; j < 8; ++j) {
        int col = n0 + wn + 8 * j + 2 * lc;
        float sc0 = so[col], sc1 = so[col + 1];
#pragma unroll
        for (int i = 0; i < 4; ++i) {
#pragma unroll
            for (int h2 = 0; h2 < 2; ++h2) {
                int m = m0 + wm + 16 * i + lr + 8 * h2;
                float2 o = make_float2(acc[i][j][2 * h2 + 0] * sc0,
                                       acc[i][j][2 * h2 + 1] * sc1);
                *reinterpret_cast<float2*>(out + (size_t)m * 4096 + col) = o;
            }
        }
    }
}

// =============================================================================
extern "C" void kernel_launch(void* const* d_in, const int* in_sizes, int n_in,
                              void* d_out, int out_size)
{
    const float* X    = (const float*)d_in[0];
    const float* sq   = (const float*)d_in[3];
    const float* bq   = (const float*)d_in[4];
    const float* sk   = (const float*)d_in[6];
    const float* bk   = (const float*)d_in[7];
    const float* sv   = (const float*)d_in[9];
    const float* so   = (const float*)d_in[11];
    const int*   wq   = (const int*)d_in[2];
    const int*   wk   = (const int*)d_in[5];
    const int*   wv   = (const int*)d_in[8];
    const int*   wo   = (const int*)d_in[10];
    float* out = (float*)d_out;

    cudaFuncSetAttribute(qkv_h,   cudaFuncAttributeMaxDynamicSharedMemorySize, SMEM_H);
    cudaFuncSetAttribute(o_h,     cudaFuncAttributeMaxDynamicSharedMemorySize, SMEM_H);
    cudaFuncSetAttribute(flash_h, cudaFuncAttributeMaxDynamicSharedMemorySize, FLASH_SMEM);

    __half* Xh = nullptr; cudaGetSymbolAddress((void**)&Xh, g_Xh);
    __half* W  = nullptr; cudaGetSymbolAddress((void**)&W,  g_W);
    __half* Wo = nullptr; cudaGetSymbolAddress((void**)&Wo, g_Wo);

    // prep: X f32->f16; weights int32->f16 (exact)
    x2h_kernel<<<(2048 * 4096 / 8 + 255) / 256, 256>>>(X, Xh, 2048 * 4096 / 8);
    w2h_kernel<<<(4096 * 4096 / 8 + 255) / 256, 256>>>(wq, W,               4096 * 4096 / 8);
    w2h_kernel<<<(1024 * 4096 / 8 + 255) / 256, 256>>>(wk, W + 4096 * 4096, 1024 * 4096 / 8);
    w2h_kernel<<<(1024 * 4096 / 8 + 255) / 256, 256>>>(wv, W + 5120 * 4096, 1024 * 4096 / 8);
    w2h_kernel<<<(4096 * 4096 / 8 + 255) / 256, 256>>>(wo, Wo,              4096 * 4096 / 8);

    qkv_h<<<dim3(8, 48), 256, SMEM_H>>>(sq, bq, sk, bk, sv);
    flash_h<<<dim3(64, 8), 256, FLASH_SMEM>>>();
    o_h<<<dim3(8, 32), 256, SMEM_H>>>(so, out);
}

// round 10
// speedup vs baseline: 4.3085x; 1.0337x over previous
#include <cuda_runtime.h>
#include <cuda_fp16.h>
#include <cstdint>

// B=2, S=1024, H=4096, NH=32, NKV=8, HD=128, GROUPS=4, M=B*S=2048
// All GEMMs: fp16 mma.m16n8k16 + fp32 accum. Fragments fed via ldmatrix.x4
// (trans for V). Projection GEMMs use a 3-stage cp.async pipeline.

// ---------------- scratch (static __device__, no allocations) ----------------
__device__ static __half g_Xh[2048 * 4096];           // fp16 X
__device__ static __half g_W [6144 * 4096];           // q,k,v weights fp16
__device__ static __half g_Wo[4096 * 4096];           // Wo fp16
__device__ static __half g_Q[2 * 32 * 1024 * 128];    // [B,NH,S,HD]
__device__ static __half g_K[2 * 8 * 1024 * 128];     // [B,NKV,S,HD]
__device__ static __half g_V[2 * 8 * 1024 * 128];     // [B,NKV,S,HD] natural layout
__device__ static __half g_AO[2048 * 4096];           // [B*S, NH*HD]

// ---------------- helpers ----------------
__device__ __forceinline__ void cpa16(void* dst, const void* src) {
    uint32_t s = static_cast<uint32_t>(__cvta_generic_to_shared(dst));
    asm volatile("cp.async.cg.shared.global [%0], [%1], 16;\n" :: "r"(s), "l"(src));
}
#define CP_COMMIT() asm volatile("cp.async.commit_group;\n")
#define CP_WAIT1()  asm volatile("cp.async.wait_group 1;\n")
#define CP_WAIT0()  asm volatile("cp.async.wait_group 0;\n")

__device__ __forceinline__ void mma_f16(float d[4], const uint32_t a[4], uint32_t b0, uint32_t b1) {
    asm volatile(
        "mma.sync.aligned.m16n8k16.row.col.f32.f16.f16.f32 "
        "{%0,%1,%2,%3},{%4,%5,%6,%7},{%8,%9},{%0,%1,%2,%3};\n"
        : "+f"(d[0]), "+f"(d[1]), "+f"(d[2]), "+f"(d[3])
        : "r"(a[0]), "r"(a[1]), "r"(a[2]), "r"(a[3]), "r"(b0), "r"(b1));
}
__device__ __forceinline__ void ldm4(uint32_t r[4], uint32_t addr) {
    asm volatile("ldmatrix.sync.aligned.m8n8.x4.shared.b16 {%0,%1,%2,%3}, [%4];"
        : "=r"(r[0]), "=r"(r[1]), "=r"(r[2]), "=r"(r[3]) : "r"(addr));
}
__device__ __forceinline__ void ldm4t(uint32_t r[4], uint32_t addr) {
    asm volatile("ldmatrix.sync.aligned.m8n8.x4.trans.shared.b16 {%0,%1,%2,%3}, [%4];"
        : "=r"(r[0]), "=r"(r[1]), "=r"(r[2]), "=r"(r[3]) : "r"(addr));
}
__device__ __forceinline__ uint32_t ldu32(const __half* p) {
    return *reinterpret_cast<const uint32_t*>(p);
}

// ---------------- prep kernels ----------------
__global__ __launch_bounds__(256) void w2h_kernel(const int* __restrict__ src,
                                                  __half* __restrict__ dst, int n8) {
    int i = blockIdx.x * 256 + threadIdx.x;
    if (i >= n8) return;
    const int4* s = reinterpret_cast<const int4*>(src) + i * 2;
    int4 a = s[0], b = s[1];
    __half h[8];
    h[0] = __int2half_rn(a.x); h[1] = __int2half_rn(a.y);
    h[2] = __int2half_rn(a.z); h[3] = __int2half_rn(a.w);
    h[4] = __int2half_rn(b.x); h[5] = __int2half_rn(b.y);
    h[6] = __int2half_rn(b.z); h[7] = __int2half_rn(b.w);
    reinterpret_cast<uint4*>(dst)[i] = *reinterpret_cast<const uint4*>(h);
}
__global__ __launch_bounds__(256) void x2h_kernel(const float* __restrict__ src,
                                                  __half* __restrict__ dst, int n8) {
    int i = blockIdx.x * 256 + threadIdx.x;
    if (i >= n8) return;
    const float4* s = reinterpret_cast<const float4*>(src) + i * 2;
    float4 a = s[0], b = s[1];
    __half h[8];
    h[0] = __float2half_rn(a.x); h[1] = __float2half_rn(a.y);
    h[2] = __float2half_rn(a.z); h[3] = __float2half_rn(a.w);
    h[4] = __float2half_rn(b.x); h[5] = __float2half_rn(b.y);
    h[6] = __float2half_rn(b.z); h[7] = __float2half_rn(b.w);
    reinterpret_cast<uint4*>(dst)[i] = *reinterpret_cast<const uint4*>(h);
}

// ---------------- fp16 GEMM core ----------------
// CTA 256x128, kc=64 halves, 3-stage pipeline. pitch 72 halves (144 B).
#define HP 72
#define AH (256 * HP)
#define BH (128 * HP)
#define BUFH (AH + BH)                // halves per stage
#define SMEM_H3 (3 * BUFH * 2)        // 165888 B

__device__ __forceinline__ void load_tileA_h(__half* dst, const __half* src, int rs, int t) {
    int c = t & 7, mb = t >> 3;
#pragma unroll
    for (int p = 0; p < 8; ++p) {
        int m = mb + 32 * p;
        cpa16(dst + m * HP + 8 * c, src + (size_t)m * rs + 8 * c);
    }
}
__device__ __forceinline__ void load_tileB_h(__half* dst, const __half* src, int rs, int t) {
    int c = t & 7, nb = t >> 3;
#pragma unroll
    for (int p = 0; p < 4; ++p) {
        int n = nb + 32 * p;
        cpa16(dst + n * HP + 8 * c, src + (size_t)n * rs + 8 * c);
    }
}

// one kc=64 chunk via ldmatrix: warp tile 64x64, 4 m-tiles x 8 n-tiles.
__device__ __forceinline__ void compute_h64(uint32_t sAa, uint32_t sBa,
                                            float acc[4][8][4], int lane, int wm, int wn) {
    const int arow = ((lane >> 3) & 1) * 8 + (lane & 7);   // + koff via lane>>4
    const int acol = ((lane >> 4) & 1) * 8;
    const int brow = ((lane >> 4) & 1) * 8 + (lane & 7);
    const int bcol = ((lane >> 3) & 1) * 8;
#pragma unroll
    for (int ks = 0; ks < 4; ++ks) {
        uint32_t af[4][4], bf[4][4];
#pragma unroll
        for (int i = 0; i < 4; ++i)
            ldm4(af[i], sAa + ((wm + 16 * i + arow) * HP + 16 * ks + acol) * 2);
#pragma unroll
        for (int jj = 0; jj < 4; ++jj)
            ldm4(bf[jj], sBa + ((wn + 16 * jj + brow) * HP + 16 * ks + bcol) * 2);
#pragma unroll
        for (int i = 0; i < 4; ++i)
#pragma unroll
            for (int jj = 0; jj < 4; ++jj) {
                mma_f16(acc[i][2 * jj],     af[i], bf[jj][0], bf[jj][1]);
                mma_f16(acc[i][2 * jj + 1], af[i], bf[jj][2], bf[jj][3]);
            }
    }
}

// ---------------- GEMM 1: fused QKV projection ---------------- grid (8m, 48n)
__global__ __launch_bounds__(256) void qkv_h(
    const float* __restrict__ sq, const float* __restrict__ bq,
    const float* __restrict__ sk, const float* __restrict__ bk,
    const float* __restrict__ sv)
{
    extern __shared__ __half smh[];
    const uint32_t sbase = static_cast<uint32_t>(__cvta_generic_to_shared(smh));
    const int t = threadIdx.x, lane = t & 31, w = t >> 5;
    const int wm = (w >> 1) * 64, wn = (w & 1) * 64;
    const int m0 = blockIdx.x * 256, n0 = blockIdx.y * 128;

    float acc[4][8][4];
#pragma unroll
    for (int i = 0; i < 4; ++i)
#pragma unroll
        for (int j = 0; j < 8; ++j)
#pragma unroll
            for (int q = 0; q < 4; ++q) acc[i][j][q] = 0.f;

    const __half* Ab = g_Xh + (size_t)m0 * 4096;
    const __half* Bb = g_W + (size_t)n0 * 4096;

    load_tileA_h(smh, Ab, 4096, t);
    load_tileB_h(smh + AH, Bb, 4096, t);
    CP_COMMIT();
    load_tileA_h(smh + BUFH, Ab + 64, 4096, t);
    load_tileB_h(smh + BUFH + AH, Bb + 64, 4096, t);
    CP_COMMIT();
    for (int it = 0; it < 64; ++it) {
        CP_WAIT1();
        __syncthreads();
        if (it + 2 < 64) {
            int nb = (it + 2) % 3;
            load_tileA_h(smh + nb * BUFH, Ab + (it + 2) * 64, 4096, t);
            load_tileB_h(smh + nb * BUFH + AH, Bb + (it + 2) * 64, 4096, t);
        }
        CP_COMMIT();
        uint32_t boff = sbase + (uint32_t)((it % 3) * BUFH * 2);
        compute_h64(boff, boff + AH * 2, acc, lane, wm, wn);
    }

    // epilogue: dequant + bias + fp16 round + head scatter
    int region, nloc;
    const float* scale; const float* bias;
    if (n0 < 4096)      { region = 0; nloc = n0;        scale = sq; bias = bq; }
    else if (n0 < 5120) { region = 1; nloc = n0 - 4096; scale = sk; bias = bk; }
    else                { region = 2; nloc = n0 - 5120; scale = sv; bias = nullptr; }
    const int head = nloc >> 7;
    const int lr = lane >> 2, lc = lane & 3;
#pragma unroll
    for (int j = 0; j < 8; ++j) {
        int col = wn + 8 * j + 2 * lc;
        int nl = nloc + col;
        float sc0 = scale[nl], sc1 = scale[nl + 1];
        float bb0 = bias ? bias[nl] : 0.f, bb1 = bias ? bias[nl + 1] : 0.f;
#pragma unroll
        for (int i = 0; i < 4; ++i) {
#pragma unroll
            for (int h2 = 0; h2 < 2; ++h2) {
                int m = m0 + wm + 16 * i + lr + 8 * h2;
                int b = m >> 10, s = m & 1023;
                float v0 = acc[i][j][2 * h2 + 0] * sc0 + bb0;
                float v1 = acc[i][j][2 * h2 + 1] * sc1 + bb1;
                __half* dst;
                if (region == 0)      dst = g_Q + ((size_t)((b * 32 + head) * 1024 + s)) * 128 + col;
                else if (region == 1) dst = g_K + ((size_t)((b * 8 + head) * 1024 + s)) * 128 + col;
                else                  dst = g_V + ((size_t)((b * 8 + head) * 1024 + s)) * 128 + col;
                *reinterpret_cast<__half2*>(dst) = __floats2half2_rn(v0, v1);
            }
        }
    }
}

// ---------------- fused causal flash attention (fp16) ---------------- grid (64, 8)
// sK [2][64][136], sV [2][64][136] (natural [key][d]), sP [128][72] halves.
#define FKH 136
#define FVH 136
#define FPH 72
#define SKH (64 * FKH)
#define SVH (64 * FVH)
#define FLASH_SMEM ((2 * SKH + 2 * SVH + 128 * FPH) * 2)   // 88064 B

__device__ __forceinline__ void flash_loadT(__half* dst, const __half* src, int n0, int t) {
    int c = t & 15, rb = t >> 4;
#pragma unroll
    for (int p = 0; p < 4; ++p) {
        int r = rb + 16 * p;
        cpa16(dst + r * FKH + 8 * c, src + (size_t)(n0 + r) * 128 + 8 * c);
    }
}

__global__ __launch_bounds__(256, 1) void flash_h()
{
    extern __shared__ __half smh[];
    __half* sK = smh;
    __half* sV = smh + 2 * SKH;
    __half* sP = sV + 2 * SVH;
    const uint32_t sKa0 = static_cast<uint32_t>(__cvta_generic_to_shared(sK));
    const uint32_t sVa0 = static_cast<uint32_t>(__cvta_generic_to_shared(sV));
    const uint32_t sPa  = static_cast<uint32_t>(__cvta_generic_to_shared(sP));

    const int t = threadIdx.x, lane = t & 31, w = t >> 5;
    const int lr = lane >> 2, lc = lane & 3;
    const int arow = ((lane >> 3) & 1) * 8 + (lane & 7);
    const int acol = ((lane >> 4) & 1) * 8;
    const int brow = ((lane >> 4) & 1) * 8 + (lane & 7);
    const int bcol = ((lane >> 3) & 1) * 8;
    const int z = blockIdx.x, mt = 7 - blockIdx.y;   // heavy tiles first
    const int m0 = mt * 128;
    const int niter = 2 * mt + 2;
    const int b = z >> 5, h = z & 31, kvh = h >> 2;

    const __half* Qp = g_Q + (size_t)(b * 32 + h) * 131072;
    const __half* Kp = g_K + (size_t)(b * 8 + kvh) * 131072;
    const __half* Vp = g_V + (size_t)(b * 8 + kvh) * 131072;

    // stage Q: rows 0-63 -> sK buf0, rows 64-127 -> sV buf0 (both pitch FKH)
    {
        int c = t & 15, rb = t >> 4;
#pragma unroll
        for (int p = 0; p < 8; ++p) {
            int r = rb + 16 * p;
            __half* dst = (r < 64) ? (sK + r * FKH + 8 * c)
                                   : (sV + (r - 64) * FKH + 8 * c);
            cpa16(dst, Qp + (size_t)(m0 + r) * 128 + 8 * c);
        }
        CP_COMMIT(); CP_WAIT0();
    }
    __syncthreads();

    // extract Q fragments: 8 k16 steps x 4 regs
    uint32_t qf[8][4];
    {
        const __half* base = (w < 4) ? sK : sV;
        int rb2 = (w < 4) ? 16 * w : 16 * w - 64;
#pragma unroll
        for (int s = 0; s < 8; ++s) {
            const __half* p = base + (rb2 + lr) * FKH + 16 * s + 2 * lc;
            qf[s][0] = ldu32(p);
            qf[s][1] = ldu32(p + 8 * FKH);
            qf[s][2] = ldu32(p + 8);
            qf[s][3] = ldu32(p + 8 * FKH + 8);
        }
    }
    __syncthreads();

    float oacc[16][4];
#pragma unroll
    for (int j = 0; j < 16; ++j)
#pragma unroll
        for (int q = 0; q < 4; ++q) oacc[j][q] = 0.f;
    float mrow[2] = {-1e38f, -1e38f};
    float lrow[2] = {0.f, 0.f};

    flash_loadT(sK, Kp, 0, t);
    flash_loadT(sV, Vp, 0, t);
    CP_COMMIT();

    const float sscale = 0.08838834764831845f;   // 1/sqrt(128)

    for (int it = 0; it < niter; ++it) {
        if (it + 1 < niter) {
            int nb = (it + 1) & 1;
            flash_loadT(sK + nb * SKH, Kp, (it + 1) * 64, t);
            flash_loadT(sV + nb * SVH, Vp, (it + 1) * 64, t);
            CP_COMMIT(); CP_WAIT1();
        } else CP_WAIT0();
        __syncthreads();

        const int buf = it & 1;
        const uint32_t K0a = sKa0 + buf * SKH * 2;
        const uint32_t V0a = sVa0 + buf * SVH * 2;
        const int n0 = it * 64;

        // ---- S = Q K^T (warp: 16 rows x 64 keys), ldmatrix K frags
        float sacc[8][4];
#pragma unroll
        for (int j = 0; j < 8; ++j)
#pragma unroll
            for (int q = 0; q < 4; ++q) sacc[j][q] = 0.f;
#pragma unroll
        for (int s = 0; s < 8; ++s) {
            uint32_t kf[4][4];
#pragma unroll
            for (int jj = 0; jj < 4; ++jj)
                ldm4(kf[jj], K0a + ((16 * jj + brow) * FKH + 16 * s + bcol) * 2);
#pragma unroll
            for (int jj = 0; jj < 4; ++jj) {
                mma_f16(sacc[2 * jj],     qf[s], kf[jj][0], kf[jj][1]);
                mma_f16(sacc[2 * jj + 1], qf[s], kf[jj][2], kf[jj][3]);
            }
        }

        // ---- scale + causal mask + online softmax
#pragma unroll
        for (int d = 0; d < 2; ++d) {
            const int grow = m0 + 16 * w + lr + 8 * d;
            float rm = -1e38f;
#pragma unroll
            for (int j = 0; j < 8; ++j) {
                int c0 = n0 + 8 * j + 2 * lc;
                float v0 = sacc[j][2 * d]     * sscale;
                float v1 = sacc[j][2 * d + 1] * sscale;
                if (c0     > grow) v0 = -1e30f;
                if (c0 + 1 > grow) v1 = -1e30f;
                sacc[j][2 * d]     = v0;
                sacc[j][2 * d + 1] = v1;
                rm = fmaxf(rm, fmaxf(v0, v1));
            }
            rm = fmaxf(rm, __shfl_xor_sync(0xffffffffu, rm, 1));
            rm = fmaxf(rm, __shfl_xor_sync(0xffffffffu, rm, 2));
            float newm = fmaxf(mrow[d], rm);
            float f = __expf(mrow[d] - newm);
            float rs = 0.f;
#pragma unroll
            for (int j = 0; j < 8; ++j) {
                float p0 = __expf(sacc[j][2 * d]     - newm);
                float p1 = __expf(sacc[j][2 * d + 1] - newm);
                rs += p0 + p1;
                __half2* pp = reinterpret_cast<__half2*>(
                    sP + (16 * w + lr + 8 * d) * FPH + 8 * j + 2 * lc);
                *pp = __floats2half2_rn(p0, p1);
            }
            rs += __shfl_xor_sync(0xffffffffu, rs, 1);
            rs += __shfl_xor_sync(0xffffffffu, rs, 2);
            lrow[d] = lrow[d] * f + rs;
            mrow[d] = newm;
#pragma unroll
            for (int j2 = 0; j2 < 16; ++j2) {
                oacc[j2][2 * d]     *= f;
                oacc[j2][2 * d + 1] *= f;
            }
        }
        __syncwarp();

        // ---- O += P V  (warp: 16 rows x 128 d): ldmatrix P, trans-ldmatrix V
#pragma unroll
        for (int s = 0; s < 4; ++s) {
            uint32_t af[4];
            ldm4(af, sPa + ((16 * w + arow) * FPH + 16 * s + acol) * 2);
#pragma unroll
            for (int jj = 0; jj < 8; ++jj) {
                uint32_t vf[4];
                ldm4t(vf, V0a + ((16 * s + arow) * FVH + 16 * jj + acol) * 2);
                mma_f16(oacc[2 * jj],     af, vf[0], vf[1]);
                mma_f16(oacc[2 * jj + 1], af, vf[2], vf[3]);
            }
        }
        __syncthreads();
    }

    // ---- epilogue: O /= l, fp16 round, write [B*S, NH*HD]
#pragma unroll
    for (int d = 0; d < 2; ++d) {
        float inv = 1.f / lrow[d];
        int grow = m0 + 16 * w + lr + 8 * d;
        __half* orow = g_AO + ((size_t)(b * 1024 + grow)) * 4096 + h * 128;
#pragma unroll
        for (int j2 = 0; j2 < 16; ++j2) {
            __half2* dst = reinterpret_cast<__half2*>(orow + 8 * j2 + 2 * lc);
            *dst = __floats2half2_rn(oacc[j2][2 * d] * inv, oacc[j2][2 * d + 1] * inv);
        }
    }
}

// ---------------- GEMM 4: out = AO @ Wo^T * so ---------------- grid (8m, 32n)
__global__ __launch_bounds__(256) void o_h(const float* __restrict__ so,
                                           float* __restrict__ out)
{
    extern __shared__ __half smh[];
    const uint32_t sbase = static_cast<uint32_t>(__cvta_generic_to_shared(smh));
    const int t = threadIdx.x, lane = t & 31, w = t >> 5;
    const int wm = (w >> 1) * 64, wn = (w & 1) * 64;
    const int m0 = blockIdx.x * 256, n0 = blockIdx.y * 128;

    float acc[4][8][4];
#pragma unroll
    for (int i = 0; i < 4; ++i)
#pragma unroll
        for (int j = 0; j < 8; ++j)
#pragma unroll
            for (int q = 0; q < 4; ++q) acc[i][j][q] = 0.f;

    const __half* Ab = g_AO + (size_t)m0 * 4096;
    const __half* Bb = g_Wo + (size_t)n0 * 4096;

    load_tileA_h(smh, Ab, 4096, t);
    load_tileB_h(smh + AH, Bb, 4096, t);
    CP_COMMIT();
    load_tileA_h(smh + BUFH, Ab + 64, 4096, t);
    load_tileB_h(smh + BUFH + AH, Bb + 64, 4096, t);
    CP_COMMIT();
    for (int it = 0; it < 64; ++it) {
        CP_WAIT1();
        __syncthreads();
        if (it + 2 < 64) {
            int nb = (it + 2) % 3;
            load_tileA_h(smh + nb * BUFH, Ab + (it + 2) * 64, 4096, t);
            load_tileB_h(smh + nb * BUFH + AH, Bb + (it + 2) * 64, 4096, t);
        }
        CP_COMMIT();
        uint32_t boff = sbase + (uint32_t)((it % 3) * BUFH * 2);
        compute_h64(boff, boff + AH * 2, acc, lane, wm, wn);
    }

    const int lr = lane >> 2, lc = lane & 3;
#pragma unroll
    for (int j = 0; j < 8; ++j) {
        int col = n0 + wn + 8 * j + 2 * lc;
        float sc0 = so[col], sc1 = so[col + 1];
#pragma unroll
        for (int i = 0; i < 4; ++i) {
#pragma unroll
            for (int h2 = 0; h2 < 2; ++h2) {
                int m = m0 + wm + 16 * i + lr + 8 * h2;
                float2 o = make_float2(acc[i][j][2 * h2 + 0] * sc0,
                                       acc[i][j][2 * h2 + 1] * sc1);
                *reinterpret_cast<float2*>(out + (size_t)m * 4096 + col) = o;
            }
        }
    }
}

// =============================================================================
extern "C" void kernel_launch(void* const* d_in, const int* in_sizes, int n_in,
                              void* d_out, int out_size)
{
    const float* X    = (const float*)d_in[0];
    const float* sq   = (const float*)d_in[3];
    const float* bq   = (const float*)d_in[4];
    const float* sk   = (const float*)d_in[6];
    const float* bk   = (const float*)d_in[7];
    const float* sv   = (const float*)d_in[9];
    const float* so   = (const float*)d_in[11];
    const int*   wq   = (const int*)d_in[2];
    const int*   wk   = (const int*)d_in[5];
    const int*   wv   = (const int*)d_in[8];
    const int*   wo   = (const int*)d_in[10];
    float* out = (float*)d_out;

    cudaFuncSetAttribute(qkv_h,   cudaFuncAttributeMaxDynamicSharedMemorySize, SMEM_H3);
    cudaFuncSetAttribute(o_h,     cudaFuncAttributeMaxDynamicSharedMemorySize, SMEM_H3);
    cudaFuncSetAttribute(flash_h, cudaFuncAttributeMaxDynamicSharedMemorySize, FLASH_SMEM);

    __half* Xh = nullptr; cudaGetSymbolAddress((void**)&Xh, g_Xh);
    __half* W  = nullptr; cudaGetSymbolAddress((void**)&W,  g_W);
    __half* Wo = nullptr; cudaGetSymbolAddress((void**)&Wo, g_Wo);

    x2h_kernel<<<(2048 * 4096 / 8 + 255) / 256, 256>>>(X, Xh, 2048 * 4096 / 8);
    w2h_kernel<<<(4096 * 4096 / 8 + 255) / 256, 256>>>(wq, W,               4096 * 4096 / 8);
    w2h_kernel<<<(1024 * 4096 / 8 + 255) / 256, 256>>>(wk, W + 4096 * 4096, 1024 * 4096 / 8);
    w2h_kernel<<<(1024 * 4096 / 8 + 255) / 256, 256>>>(wv, W + 5120 * 4096, 1024 * 4096 / 8);
    w2h_kernel<<<(4096 * 4096 / 8 + 255) / 256, 256>>>(wo, Wo,              4096 * 4096 / 8);

    qkv_h<<<dim3(8, 48), 256, SMEM_H3>>>(sq, bq, sk, bk, sv);
    flash_h<<<dim3(64, 8), 256, FLASH_SMEM>>>();
    o_h<<<dim3(8, 32), 256, SMEM_H3>>>(so, out);
}